// round 17
// baseline (speedup 1.0000x reference)
#include <cuda_runtime.h>
#include <cuda_bf16.h>
#include <cstdint>

// Problem constants
#define BSESS 1024
#define NNODE 32
#define SLEN  50
#define HD    256
#define VOC   50000

// Scores GEMM config: C[1024,50000] split-bf16.
#define KC      64
#define NCHUNK  8
#define TILEB   16384              // 128 rows x 128 B
#define STAGE3  (3*TILEB)          // B + Ah + Al = 48 KB
#define SMEM_SZ (2*STAGE3)         // 96 KB double buffered

#define CONVC   296                // conv_split CTAs (2/SM, co-residable)

// Chain-MMA config: 64 CTAs x 16 rows, 512 threads, tensor-core SAN chain.
#define W3OFFB  262144             // bf16-element offset of W3 in g_Wh/g_Wl
// smem: sv/sx/sa/st fp32 16x256 (4x16KB) | ah,al bf16 8 chunk-tiles (2x16KB) |
//       W ring: 4 x 32KB
#define CH_SV   0
#define CH_SX   16384
#define CH_SA   32768
#define CH_ST   49152
#define CH_AH   65536
#define CH_AL   81920
#define CH_WB   98304
#define CH2_SMEM (98304 + 4*32768)   // 229376 B = 224 KB

// Scratch
__device__ float g_sh[BSESS*HD];
__device__ __nv_bfloat16 g_Wh[4*HD*HD + 2*HD*HD];
__device__ __nv_bfloat16 g_Wl[4*HD*HD + 2*HD*HD];
__device__ __nv_bfloat16 g_Bh[(size_t)VOC*HD];
__device__ __nv_bfloat16 g_Bl[(size_t)VOC*HD];
__device__ __nv_bfloat16 g_Ah[BSESS*HD];
__device__ __nv_bfloat16 g_Al[BSESS*HD];

// ---------------------------------------------------------------------------
// Helpers (baseline ISA only)
// ---------------------------------------------------------------------------
__device__ __forceinline__ uint32_t smem_u32(const void* p) {
    uint32_t a;
    asm("{ .reg .u64 t; cvta.to.shared.u64 t, %1; cvt.u32.u64 %0, t; }"
        : "=r"(a) : "l"(p));
    return a;
}
__device__ __forceinline__ void cp16(uint32_t dst, const void* src) {
    asm volatile("cp.async.cg.shared.global [%0], [%1], 16;"
                 :: "r"(dst), "l"(src));
}
#define CP_COMMIT() asm volatile("cp.async.commit_group;" ::: "memory")
#define CP_WAIT(n)  asm volatile("cp.async.wait_group %0;" :: "n"(n) : "memory")

__device__ __forceinline__ uint32_t sw128(uint32_t x) {
    return x ^ ((x >> 3) & 0x70);
}
__device__ __forceinline__ void ldsm4(uint32_t* r, uint32_t addr) {
    asm volatile("ldmatrix.sync.aligned.m8n8.x4.shared.b16 {%0,%1,%2,%3}, [%4];"
                 : "=r"(r[0]), "=r"(r[1]), "=r"(r[2]), "=r"(r[3]) : "r"(addr));
}
__device__ __forceinline__ void mma16816(float* c, const uint32_t* a,
                                         const uint32_t* b) {
    asm volatile(
        "mma.sync.aligned.m16n8k16.row.col.f32.bf16.bf16.f32 "
        "{%0,%1,%2,%3}, {%4,%5,%6,%7}, {%8,%9}, {%0,%1,%2,%3};"
        : "+f"(c[0]), "+f"(c[1]), "+f"(c[2]), "+f"(c[3])
        : "r"(a[0]), "r"(a[1]), "r"(a[2]), "r"(a[3]), "r"(b[0]), "r"(b[1]));
}

// ---------------------------------------------------------------------------
// One-time weight hi/lo split. W layout [out_col][k] (k contiguous) is ALREADY
// the mma B-operand layout; no transpose needed.
// ---------------------------------------------------------------------------
__global__ void wsplit(const float* __restrict__ Wv,
                       const float* __restrict__ Wo,
                       const float* __restrict__ d1w,
                       const float* __restrict__ d2w,
                       const float* __restrict__ W3w) {
    int m = blockIdx.z;
    const float* src; int n4; size_t off;
    if (m < 4) {
        src = (m==0)?Wv:(m==1)?Wo:(m==2)?d1w:d2w;
        n4 = 16384; off = (size_t)m*65536;
    } else {
        src = W3w; n4 = 32768; off = W3OFFB;
    }
    int i = blockIdx.x*256 + threadIdx.x;
    if (i >= n4) return;
    float4 v = ((const float4*)src)[i];
    __nv_bfloat16 h0 = __float2bfloat16(v.x), h1 = __float2bfloat16(v.y),
                  h2 = __float2bfloat16(v.z), h3 = __float2bfloat16(v.w);
    __nv_bfloat16 l0 = __float2bfloat16(v.x - __bfloat162float(h0));
    __nv_bfloat16 l1 = __float2bfloat16(v.y - __bfloat162float(h1));
    __nv_bfloat16 l2 = __float2bfloat16(v.z - __bfloat162float(h2));
    __nv_bfloat16 l3 = __float2bfloat16(v.w - __bfloat162float(h3));
    ((__nv_bfloat162*)(g_Wh+off))[i*2+0] = __nv_bfloat162(h0, h1);
    ((__nv_bfloat162*)(g_Wh+off))[i*2+1] = __nv_bfloat162(h2, h3);
    ((__nv_bfloat162*)(g_Wl+off))[i*2+0] = __nv_bfloat162(l0, l1);
    ((__nv_bfloat162*)(g_Wl+off))[i*2+1] = __nv_bfloat162(l2, l3);
}

// ---------------------------------------------------------------------------
// Tensor-core chain: vn gather -> 13 split-bf16 mma GEMM steps -> s_h + split.
// 64 CTAs x 16 rows, 512 threads (16 warps = 4/SMSP; warp w owns n-cols
// w*16..w*16+15 -> mma/warp halved vs 8-warp version). W streams through a
// 4-buffer ring with ONE barrier pair per 2 chunks. Identical mma order per
// output element as the 8-warp version -> bit-identical results.
// ---------------------------------------------------------------------------
__global__ void __launch_bounds__(512, 1)
chain_mma(const float* __restrict__ node_emb,
          const float* __restrict__ itemset_len,
          const int*   __restrict__ sequence,
          const float* __restrict__ bv,  const float* __restrict__ bo,
          const float* __restrict__ d1b, const float* __restrict__ d2b,
          const float* __restrict__ W3b) {
    extern __shared__ char cs8[];
    float* sv = (float*)(cs8 + CH_SV);
    float* sx = (float*)(cs8 + CH_SX);
    float* sa = (float*)(cs8 + CH_SA);
    float* st = (float*)(cs8 + CH_ST);
    char*  ah = cs8 + CH_AH;
    char*  al = cs8 + CH_AL;
    uint32_t ah_u = smem_u32(ah), al_u = smem_u32(al);
    uint32_t wb_u = smem_u32(cs8 + CH_WB);

    int tid = threadIdx.x, w = tid >> 5, lane = tid & 31;
    int q = lane >> 3, r8 = lane & 7;
    int b0row = blockIdx.x * 16;

    // ---- v_n gather: warp w -> row w ----
    {
        int row = w;
        int b = b0row + row;
        int t = b*SLEN + (SLEN-1);
        int s0 = sequence[t*3+0], s1 = sequence[t*3+1], s2 = sequence[t*3+2];
        float inv = 1.f / itemset_len[t];
        const float* base = node_emb + (size_t)b*NNODE*HD;
        #pragma unroll
        for (int p = 0; p < 2; p++) {
            int c = lane*8 + p*4;
            float4 acc = make_float4(0.f, 0.f, 0.f, 0.f);
            if (s0 != NNODE) { float4 v = *(const float4*)&base[s0*HD + c];
                acc.x+=v.x; acc.y+=v.y; acc.z+=v.z; acc.w+=v.w; }
            if (s1 != NNODE) { float4 v = *(const float4*)&base[s1*HD + c];
                acc.x+=v.x; acc.y+=v.y; acc.z+=v.z; acc.w+=v.w; }
            if (s2 != NNODE) { float4 v = *(const float4*)&base[s2*HD + c];
                acc.x+=v.x; acc.y+=v.y; acc.z+=v.z; acc.w+=v.w; }
            acc.x*=inv; acc.y*=inv; acc.z*=inv; acc.w*=inv;
            *(float4*)&sv[row*HD + c] = acc;
            *(float4*)&sx[row*HD + c] = acc;
        }
    }
    __syncthreads();

    // Fragment coordinates (scores_kernel scheme; warp tile = 16 rows x 16 n)
    uint32_t a_row = (uint32_t)((q & 1)*8 + r8);
    uint32_t a_kb  = (uint32_t)((q >> 1) * 16);
    uint32_t b_row = (uint32_t)(w*16 + (q >> 1)*8 + r8);
    uint32_t b_kb  = (uint32_t)((q & 1) * 16);
    int er = lane >> 2, ec = (lane & 3)*2;

    const float* btab[4] = {bv, bo, d1b, d2b};
    const float* intab[4]  = {sx, st, sa, st};
    float*       outtab[4] = {st, sa, st, sx};

    // A-convert helper indices: 512 threads, 16 rows x 256 k, 8 k per thread
    int crow = tid >> 5, ckk = lane * 8;

    for (int j = 0; j <= 12; j++) {
        bool w3 = (j == 12);
        int sp = j & 3;
        const __nv_bfloat16* Wh = g_Wh + (w3 ? W3OFFB : sp*65536);
        const __nv_bfloat16* Wl = g_Wl + (w3 ? W3OFFB : sp*65536);
        int K = w3 ? 512 : 256;
        int nkc = K / 64;            // 4 or 8 k-chunks per term
        int nch2 = 2 * nkc;          // total chunk passes (Wh + Wl)
        const float* in_s = intab[sp];
        float* out_s = outtab[sp];

        // ---- convert activations -> bf16 hi/lo chunk tiles ----
        #pragma unroll
        for (int half = 0; half < 2; half++) {
            if (half == 1 && !w3) break;
            const float* s0 = w3 ? (half ? sx : sv) : in_s;
            int cofs = half * 4;
            float4 f0 = *(const float4*)&s0[crow*HD + ckk];
            float4 f1 = *(const float4*)&s0[crow*HD + ckk + 4];
            float vals[8] = {f0.x,f0.y,f0.z,f0.w,f1.x,f1.y,f1.z,f1.w};
            uint4 hv, lv;
            __nv_bfloat162* hp = (__nv_bfloat162*)&hv;
            __nv_bfloat162* lp = (__nv_bfloat162*)&lv;
            #pragma unroll
            for (int e = 0; e < 4; e++) {
                float ax = vals[2*e], ay = vals[2*e+1];
                __nv_bfloat16 hx = __float2bfloat16(ax);
                __nv_bfloat16 hy = __float2bfloat16(ay);
                hp[e] = __nv_bfloat162(hx, hy);
                lp[e] = __nv_bfloat162(
                    __float2bfloat16(ax - __bfloat162float(hx)),
                    __float2bfloat16(ay - __bfloat162float(hy)));
            }
            int chunk = cofs + (ckk >> 6);
            uint32_t off = sw128((uint32_t)(crow*128 + (ckk & 63)*2));
            *(uint4*)(ah + chunk*2048 + off) = hv;
            *(uint4*)(al + chunk*2048 + off) = lv;
        }
        __syncthreads();

        float c[2][4];
        #pragma unroll
        for (int i = 0; i < 2; i++)
            #pragma unroll
            for (int k = 0; k < 4; k++) c[i][k] = 0.f;

        // ---- W chunk streaming (4-buffer ring, paired barriers) + mma ----
        auto wload = [&](int kc) {
            const __nv_bfloat16* Wsrc = (kc < nkc) ? Wh : Wl;
            int k0 = (kc & (nkc-1)) * 64;
            uint32_t base = wb_u + (kc & 3)*32768;
            #pragma unroll
            for (int jj = tid; jj < 2048; jj += 512) {
                int n = jj >> 3, seg = jj & 7;
                cp16(base + sw128((uint32_t)(n*128 + seg*16)),
                     Wsrc + (size_t)n*K + k0 + seg*8);
            }
        };
        wload(0); wload(1);
        CP_COMMIT();

        int npairs = nch2 >> 1;
        for (int pc = 0; pc < npairs; pc++) {
            if (pc + 1 < npairs) {
                wload(2*pc + 2); wload(2*pc + 3);
                CP_COMMIT();
                CP_WAIT(1);
            } else {
                CP_WAIT(0);
            }
            __syncthreads();
            #pragma unroll
            for (int h = 0; h < 2; h++) {
                int kc = 2*pc + h;
                uint32_t base = wb_u + (kc & 3)*32768;
                bool hiterm = (kc < nkc);
                int ca = kc & (nkc-1);
                uint32_t ab  = ah_u + ca*2048;
                uint32_t alb = al_u + ca*2048;
                #pragma unroll
                for (int ks = 0; ks < 4; ks++) {
                    uint32_t b[4];
                    ldsm4(b, base + sw128(b_row*128 + b_kb + ks*32));
                    uint32_t aswo = sw128(a_row*128 + a_kb + ks*32);
                    uint32_t a[4];
                    ldsm4(a, ab + aswo);
                    mma16816(c[0], a, b);
                    mma16816(c[1], a, b + 2);
                    if (hiterm) {
                        uint32_t a2[4];
                        ldsm4(a2, alb + aswo);
                        mma16816(c[0], a2, b);
                        mma16816(c[1], a2, b + 2);
                    }
                }
            }
            __syncthreads();
        }

        // ---- epilogue: warp w owns cols w*16 + n8*8 + ec, rows er/er+8 ----
        if (!w3) {
            const float* bias = btab[sp];
            #pragma unroll
            for (int n8 = 0; n8 < 2; n8++) {
                int cb = w*16 + n8*8 + ec;
                float b0v = bias[cb], b1v = bias[cb+1];
                float v00 = c[n8][0] + b0v, v01 = c[n8][1] + b1v;
                float v10 = c[n8][2] + b0v, v11 = c[n8][3] + b1v;
                if (sp == 2) {
                    v00 = fmaxf(v00, 0.f); v01 = fmaxf(v01, 0.f);
                    v10 = fmaxf(v10, 0.f); v11 = fmaxf(v11, 0.f);
                }
                if (sp == 3) {
                    v00 += sa[er*HD + cb];     v01 += sa[er*HD + cb + 1];
                    v10 += sa[(er+8)*HD + cb]; v11 += sa[(er+8)*HD + cb + 1];
                }
                out_s[er*HD + cb]       = v00;
                out_s[er*HD + cb + 1]   = v01;
                out_s[(er+8)*HD + cb]   = v10;
                out_s[(er+8)*HD + cb+1] = v11;
            }
            __syncthreads();
        } else {
            #pragma unroll
            for (int n8 = 0; n8 < 2; n8++) {
                int cb = w*16 + n8*8 + ec;
                float b0v = W3b[cb], b1v = W3b[cb+1];
                float vr[2][2] = {{c[n8][0] + b0v, c[n8][1] + b1v},
                                  {c[n8][2] + b0v, c[n8][3] + b1v}};
                #pragma unroll
                for (int rr = 0; rr < 2; rr++) {
                    int gr = b0row + er + rr*8;
                    #pragma unroll
                    for (int cc = 0; cc < 2; cc++) {
                        float v = vr[rr][cc];
                        g_sh[gr*HD + cb + cc] = v;
                        __nv_bfloat16 h = __float2bfloat16(v);
                        g_Ah[gr*HD + cb + cc] = h;
                        g_Al[gr*HD + cb + cc] =
                            __float2bfloat16(v - __bfloat162float(h));
                    }
                }
            }
        }
    }
}

// ---------------------------------------------------------------------------
// fp32 -> (bf16 hi, bf16 lo) split (B side). Grid-stride, co-residable.
// ---------------------------------------------------------------------------
__global__ void __launch_bounds__(256)
conv_split(const float* __restrict__ src,
           __nv_bfloat16* __restrict__ hi,
           __nv_bfloat16* __restrict__ lo, int n4) {
    for (int i = blockIdx.x*256 + threadIdx.x; i < n4; i += CONVC*256) {
        float4 v = ((const float4*)src)[i];
        __nv_bfloat16 h0 = __float2bfloat16(v.x), h1 = __float2bfloat16(v.y),
                      h2 = __float2bfloat16(v.z), h3 = __float2bfloat16(v.w);
        __nv_bfloat16 l0 = __float2bfloat16(v.x - __bfloat162float(h0));
        __nv_bfloat16 l1 = __float2bfloat16(v.y - __bfloat162float(h1));
        __nv_bfloat16 l2 = __float2bfloat16(v.z - __bfloat162float(h2));
        __nv_bfloat16 l3 = __float2bfloat16(v.w - __bfloat162float(h3));
        ((__nv_bfloat162*)hi)[i*2+0] = __nv_bfloat162(h0, h1);
        ((__nv_bfloat162*)hi)[i*2+1] = __nv_bfloat162(h2, h3);
        ((__nv_bfloat162*)lo)[i*2+0] = __nv_bfloat162(l0, l1);
        ((__nv_bfloat162*)lo)[i*2+1] = __nv_bfloat162(l2, l3);
    }
}

// ---------------------------------------------------------------------------
// Scores GEMM (mma.sync bf16, split-fp32). grid (8 m-tiles, 391 n-tiles).
// ---------------------------------------------------------------------------
__global__ void __launch_bounds__(256, 2)
scores_kernel(float* __restrict__ out) {
    extern __shared__ char smem[];
    uint32_t sb = smem_u32(smem);
    int tid = threadIdx.x, lane = tid & 31, wid = tid >> 5;
    int wm = wid >> 2, wn = wid & 3;
    int m0 = blockIdx.x * 128, n0 = blockIdx.y * 128;
    int q = lane >> 3, r8 = lane & 7;

    uint32_t a_row = (uint32_t)(wm*64 + (q & 1)*8 + r8);
    uint32_t a_kb  = (uint32_t)((q >> 1) * 16);
    uint32_t b_row = (uint32_t)(wn*32 + (q >> 1)*8 + r8);
    uint32_t b_kb  = (uint32_t)((q & 1) * 16);

    float c[4][4][4];
    #pragma unroll
    for (int i = 0; i < 4; i++)
        #pragma unroll
        for (int j = 0; j < 4; j++)
            #pragma unroll
            for (int k = 0; k < 4; k++) c[i][j][k] = 0.f;

    auto load_stage = [&](int kc, int st) {
        bool hiterm = (kc < 4);
        const __nv_bfloat16* Bsrc = hiterm ? g_Bh : g_Bl;
        int k0 = (kc & 3) * KC;
        uint32_t base = sb + st*STAGE3;
        #pragma unroll
        for (int j = tid; j < 1024; j += 256) {
            int row = j >> 3, seg = j & 7;
            uint32_t off = sw128((uint32_t)(row*128 + seg*16));
            int gr = n0 + row; if (gr > VOC-1) gr = VOC-1;
            cp16(base + off, Bsrc + (size_t)gr*HD + k0 + seg*8);
            cp16(base + TILEB + off, g_Ah + (size_t)(m0 + row)*HD + k0 + seg*8);
            if (hiterm)
                cp16(base + 2*TILEB + off,
                     g_Al + (size_t)(m0 + row)*HD + k0 + seg*8);
        }
    };

    load_stage(0, 0);
    CP_COMMIT();

    for (int kc = 0; kc < NCHUNK; kc++) {
        int st = kc & 1;
        if (kc + 1 < NCHUNK) {
            load_stage(kc + 1, st ^ 1);
            CP_COMMIT();
            CP_WAIT(1);
        } else {
            CP_WAIT(0);
        }
        __syncthreads();
        uint32_t base = sb + st*STAGE3;
        bool hiterm = (kc < 4);
        #pragma unroll
        for (int ks = 0; ks < 4; ks++) {
            uint32_t b[4][2];
            #pragma unroll
            for (int nb = 0; nb < 2; nb++) {
                uint32_t r[4];
                ldsm4(r, base + sw128((b_row + nb*16)*128 + b_kb + ks*32));
                b[nb*2+0][0] = r[0]; b[nb*2+0][1] = r[1];
                b[nb*2+1][0] = r[2]; b[nb*2+1][1] = r[3];
            }
            #pragma unroll
            for (int mb = 0; mb < 4; mb++) {
                uint32_t asw = sw128((a_row + mb*16)*128 + a_kb + ks*32);
                uint32_t a[4];
                ldsm4(a, base + TILEB + asw);
                #pragma unroll
                for (int n8 = 0; n8 < 4; n8++)
                    mma16816(c[mb][n8], a, b[n8]);
                if (hiterm) {
                    uint32_t al2[4];
                    ldsm4(al2, base + 2*TILEB + asw);
                    #pragma unroll
                    for (int n8 = 0; n8 < 4; n8++)
                        mma16816(c[mb][n8], al2, b[n8]);
                }
            }
        }
        __syncthreads();
    }

    #pragma unroll
    for (int mb = 0; mb < 4; mb++) {
        int gr0 = m0 + wm*64 + mb*16 + (lane >> 2);
        #pragma unroll
        for (int n8 = 0; n8 < 4; n8++) {
            int col = n0 + wn*32 + n8*8 + (lane & 3)*2;
            if (col < VOC) {
                *(float2*)&out[(size_t)gr0*VOC + col]     =
                    make_float2(c[mb][n8][0], c[mb][n8][1]);
                *(float2*)&out[(size_t)(gr0+8)*VOC + col] =
                    make_float2(c[mb][n8][2], c[mb][n8][3]);
            }
        }
    }
}

// ---------------------------------------------------------------------------
// y_hat[b] = dot(s_h[b], emb_weight[cue[b]])  (exact fp32 path)
// ---------------------------------------------------------------------------
__global__ void yhat_kernel(const float* __restrict__ emb,
                            const int*   __restrict__ cue,
                            float* __restrict__ out) {
    int b = blockIdx.x, tid = threadIdx.x;
    float v = g_sh[b*HD + tid] * emb[((size_t)cue[b])*HD + tid];
    #pragma unroll
    for (int o = 16; o > 0; o >>= 1) v += __shfl_down_sync(0xffffffffu, v, o);
    __shared__ float red[8];
    if ((tid & 31) == 0) red[tid >> 5] = v;
    __syncthreads();
    if (tid == 0) {
        float s = 0.f;
        #pragma unroll
        for (int i = 0; i < 8; i++) s += red[i];
        out[b] = s;
    }
}

// ---------------------------------------------------------------------------
static __nv_bfloat16 *pBh, *pBl;
static cudaStream_t sB = nullptr;
static cudaEvent_t evFork = nullptr, evConv = nullptr,
                   evChain = nullptr, evSide = nullptr;
static bool g_init = false;

static void resolve_once() {
    if (g_init) return;
    cudaGetSymbolAddress((void**)&pBh, g_Bh);
    cudaGetSymbolAddress((void**)&pBl, g_Bl);
    cudaFuncSetAttribute(scores_kernel,
                         cudaFuncAttributeMaxDynamicSharedMemorySize, SMEM_SZ);
    cudaFuncSetAttribute(chain_mma,
                         cudaFuncAttributeMaxDynamicSharedMemorySize, CH2_SMEM);
    cudaStreamCreateWithFlags(&sB, cudaStreamNonBlocking);
    cudaEventCreateWithFlags(&evFork,  cudaEventDisableTiming);
    cudaEventCreateWithFlags(&evConv,  cudaEventDisableTiming);
    cudaEventCreateWithFlags(&evChain, cudaEventDisableTiming);
    cudaEventCreateWithFlags(&evSide,  cudaEventDisableTiming);
    g_init = true;
}

extern "C" void kernel_launch(void* const* d_in, const int* in_sizes, int n_in,
                              void* d_out, int out_size) {
    const float* node_embedding = (const float*)d_in[0];
    const float* emb_weight     = (const float*)d_in[1];
    const float* itemset_len    = (const float*)d_in[2];
    const float* in_proj_w      = (const float*)d_in[3];
    const float* in_proj_b      = (const float*)d_in[4];
    const float* out_proj_w     = (const float*)d_in[5];
    const float* out_proj_b     = (const float*)d_in[6];
    const float* d1_w           = (const float*)d_in[7];
    const float* d1_b           = (const float*)d_in[8];
    const float* d2_w           = (const float*)d_in[9];
    const float* d2_b           = (const float*)d_in[10];
    const float* W3_w           = (const float*)d_in[11];
    const float* W3_b           = (const float*)d_in[12];
    const int*   sequence       = (const int*)d_in[14];
    const int*   cue            = (const int*)d_in[16];

    resolve_once();
    float* out = (float*)d_out;

    // Fork: conv_split (co-residable) on side stream.
    cudaEventRecord(evFork, 0);
    cudaStreamWaitEvent(sB, evFork, 0);
    conv_split<<<CONVC, 256, 0, sB>>>(emb_weight, pBh, pBl, VOC*HD/4);
    cudaEventRecord(evConv, sB);

    // Main: weight hi/lo split -> tensor-core SAN chain.
    wsplit<<<dim3(128, 1, 5), 256>>>(in_proj_w + 2*HD*HD, out_proj_w,
                                     d1_w, d2_w, W3_w);
    chain_mma<<<BSESS/16, 512, CH2_SMEM>>>(node_embedding, itemset_len,
                                           sequence,
                                           in_proj_b + 2*HD, out_proj_b,
                                           d1_b, d2_b, W3_b);
    cudaEventRecord(evChain, 0);

    // Side: yhat (needs chain) overlaps with scores.
    cudaStreamWaitEvent(sB, evChain, 0);
    yhat_kernel<<<BSESS, HD, 0, sB>>>(emb_weight, cue, out);
    cudaEventRecord(evSide, sB);

    // Main: scores (needs chain outputs + conv outputs).
    cudaStreamWaitEvent(0, evConv, 0);
    scores_kernel<<<dim3(8, (VOC + 127)/128), 256, SMEM_SZ>>>(out + BSESS);

    // Join side stream back into the capture-origin stream.
    cudaStreamWaitEvent(0, evSide, 0);
}